// round 15
// baseline (speedup 1.0000x reference)
#include <cuda_runtime.h>
#include <math.h>

// Per-row least-squares ternary quantization — BIT-EXACT numerics pinned in R13:
//   exact descending sort of |w| bits; ReduceWindowRewriter(16) recursive cumsum
//   (trailing pad); score = fl(fl(c*c)*rcp_rn(k)); v1 = CR divide; first-max argmax.
// R15: hand-rolled smem-resident 8-bit radix sort (4 passes, stable) replaces
// cub::BlockRadixSort (8 passes, reg-resident). Keys in smem => ~30 regs =>
// 2 CTAs/SM (occupancy 2x). Counter array padded (stride 257) for banks.

#define M_COLS   11008
#define NTHREADS 1024
#define NITEMS   11264   // 11*1024; pads (=0) sort to the FRONT ascending
#define IPW      11
#define CNT_STR  257     // padded stride: cnt[warp*257 + digit]
#define B0       688     // 11008/16
#define B1       43      // 688/16
#define B2       3

// dynamic smem layout (bytes)
#define OFF_A     0                        // u32[11264] ping  (final sorted, ascending)
#define OFF_B     45056                    // u32[11264] pong  (cs aliases after sort)
#define OFF_CNT   90112                    // u16[32*257] = 16448 (aux aliases after sort)
#define OFF_SCAN  (OFF_CNT + 16448)        // u32[32] + pad
#define SMEM_BYTES (OFF_SCAN + 160)
// post-sort aliases inside CNT region (all dead after the sort):
#define AX_S0    0        // float[704]
#define AX_W1    2816     // float[704]
#define AX_S1    5632     // float[48]
#define AX_W2    5824     // float[48]
#define AX_E2    6016     // float[8]
#define AX_REDS  6048     // float[32]
#define AX_REDJ  6176     // int[32]
#define AX_BC    6304     // float[4]

__global__ __launch_bounds__(NTHREADS, 2)
void lst_ternary_kernel(const float* __restrict__ w,
                        const int* __restrict__ skip_p,
                        float* __restrict__ out,
                        int m)
{
    extern __shared__ unsigned char smem[];
    unsigned int*   A    = (unsigned int*)(smem + OFF_A);
    unsigned int*   Bp   = (unsigned int*)(smem + OFF_B);
    unsigned short* cnt  = (unsigned short*)(smem + OFF_CNT);
    unsigned int*   saux = (unsigned int*)(smem + OFF_SCAN);

    const int tid  = threadIdx.x;
    const int lane = tid & 31;
    const int wid  = tid >> 5;
    const int row  = blockIdx.x;
    const float* wr  = w   + (long long)row * m;
    float*       owr = out + (long long)row * m;

    // ---- 1. load keys = bits of |w| (monotone for nonneg), pads = 0 ----
    #pragma unroll
    for (int i = 0; i < IPW; ++i) {
        const int idx = i * NTHREADS + tid;
        A[idx] = (idx < m) ? (__float_as_uint(wr[idx]) & 0x7fffffffu) : 0u;
    }
    __syncthreads();

    // ---- 2. stable LSD radix sort, 4 passes of 8 bits, ascending ----
    unsigned int* src = A;
    unsigned int* dst = Bp;
    const int kbase = wid * (IPW * 32) + lane;   // warp-contiguous chunks

    #pragma unroll
    for (int pass = 0; pass < 4; ++pass) {
        const int shift = pass * 8;

        // 2a. zero counters
        for (int i = tid; i < 32 * CNT_STR; i += NTHREADS) cnt[i] = 0;
        __syncthreads();

        // 2b. count: warp-private histograms, stable order
        #pragma unroll
        for (int it = 0; it < IPW; ++it) {
            const unsigned key = src[kbase + it * 32];
            const unsigned d   = (key >> shift) & 0xFFu;
            const unsigned mask = __match_any_sync(0xffffffffu, d);
            volatile unsigned short* cp = cnt + wid * CNT_STR + d;
            const unsigned prev = *cp;
            __syncwarp();
            if ((mask & ((1u << lane) - 1u)) == 0u)          // group leader
                *cp = (unsigned short)(prev + __popc(mask));
            __syncwarp();
        }
        __syncthreads();

        // 2c. exclusive scan over flat order f = digit*32 + warp
        //     thread t covers f in [8t, 8t+8): d = t>>2, w = (t&3)*8 + k
        {
            const int d  = tid >> 2;
            const int w0 = (tid & 3) * 8;
            unsigned v[8], s = 0;
            #pragma unroll
            for (int k = 0; k < 8; ++k) { v[k] = cnt[(w0 + k) * CNT_STR + d]; s += v[k]; }
            unsigned inc = s;
            #pragma unroll
            for (int o = 1; o < 32; o <<= 1) {
                unsigned u = __shfl_up_sync(0xffffffffu, inc, o);
                if (lane >= o) inc += u;
            }
            if (lane == 31) saux[wid] = inc;
            __syncthreads();
            if (wid == 0) {
                unsigned t3 = saux[lane];
                unsigned i2 = t3;
                #pragma unroll
                for (int o = 1; o < 32; o <<= 1) {
                    unsigned u = __shfl_up_sync(0xffffffffu, i2, o);
                    if (lane >= o) i2 += u;
                }
                saux[lane] = i2 - t3;                        // exclusive warp offsets
            }
            __syncthreads();
            unsigned run = saux[wid] + (inc - s);            // block-exclusive base
            #pragma unroll
            for (int k = 0; k < 8; ++k) {
                cnt[(w0 + k) * CNT_STR + d] = (unsigned short)run;
                run += v[k];
            }
        }
        __syncthreads();

        // 2d. rank & scatter (counters now hold running global bases)
        #pragma unroll
        for (int it = 0; it < IPW; ++it) {
            const unsigned key = src[kbase + it * 32];
            const unsigned d   = (key >> shift) & 0xFFu;
            const unsigned mask = __match_any_sync(0xffffffffu, d);
            volatile unsigned short* cp = cnt + wid * CNT_STR + d;
            const unsigned prev = *cp;
            __syncwarp();
            if ((mask & ((1u << lane) - 1u)) == 0u)
                *cp = (unsigned short)(prev + __popc(mask));
            __syncwarp();
            const unsigned rank = prev + __popc(mask & ((1u << lane) - 1u));
            dst[rank] = key;
        }
        __syncthreads();

        unsigned int* t = src; src = dst; dst = t;           // after 4 passes: sorted in A
    }

    // sorted ASCENDING in A; pads (0) at front. Descending view over m reals:
    //   SDESC(i) = A[NITEMS-1-i], i in [0, m)
    float*        cs   = (float*)(smem + OFF_B);             // alias pong buffer
    unsigned char* ax  = smem + OFF_CNT;                     // alias counter region
    float* S0   = (float*)(ax + AX_S0);
    float* W1   = (float*)(ax + AX_W1);
    float* S1   = (float*)(ax + AX_S1);
    float* W2   = (float*)(ax + AX_W2);
    float* E2   = (float*)(ax + AX_E2);
    float* reds = (float*)(ax + AX_REDS);
    int*   redj = (int*)(ax + AX_REDJ);
    float* bc   = (float*)(ax + AX_BC);

    #define SDESC(i) __uint_as_float(A[NITEMS - 1 - (i)])

    // ---- 3. ReduceWindowRewriter(16), recursive, trailing pad (R9 assoc) ----
    // 3a. level0 per-16 fold-left (vectorized loads/stores; identical add order)
    if (tid < B0) {
        const int b  = tid;
        const int Aw = NITEMS - 16 * (b + 1);                // 16-aligned
        const uint4* p4 = (const uint4*)(A + Aw);
        uint4 q0 = p4[0], q1 = p4[1], q2 = p4[2], q3 = p4[3];
        float c[16];
        float p = 0.0f;
        // fold order = descending addresses: q3.w, q3.z, ... q0.x
        p = __fadd_rn(p, __uint_as_float(q3.w)); c[0]  = p;
        p = __fadd_rn(p, __uint_as_float(q3.z)); c[1]  = p;
        p = __fadd_rn(p, __uint_as_float(q3.y)); c[2]  = p;
        p = __fadd_rn(p, __uint_as_float(q3.x)); c[3]  = p;
        p = __fadd_rn(p, __uint_as_float(q2.w)); c[4]  = p;
        p = __fadd_rn(p, __uint_as_float(q2.z)); c[5]  = p;
        p = __fadd_rn(p, __uint_as_float(q2.y)); c[6]  = p;
        p = __fadd_rn(p, __uint_as_float(q2.x)); c[7]  = p;
        p = __fadd_rn(p, __uint_as_float(q1.w)); c[8]  = p;
        p = __fadd_rn(p, __uint_as_float(q1.z)); c[9]  = p;
        p = __fadd_rn(p, __uint_as_float(q1.y)); c[10] = p;
        p = __fadd_rn(p, __uint_as_float(q1.x)); c[11] = p;
        p = __fadd_rn(p, __uint_as_float(q0.w)); c[12] = p;
        p = __fadd_rn(p, __uint_as_float(q0.z)); c[13] = p;
        p = __fadd_rn(p, __uint_as_float(q0.y)); c[14] = p;
        p = __fadd_rn(p, __uint_as_float(q0.x)); c[15] = p;
        float4* cs4 = (float4*)(cs + b * 16);
        cs4[0] = make_float4(c[0],  c[1],  c[2],  c[3]);
        cs4[1] = make_float4(c[4],  c[5],  c[6],  c[7]);
        cs4[2] = make_float4(c[8],  c[9],  c[10], c[11]);
        cs4[3] = make_float4(c[12], c[13], c[14], c[15]);
        S0[b] = p;
    }
    __syncthreads();
    // 3b. level1 partials over S0 (688 = 43*16 exact)
    if (tid < B1) {
        const int base = tid * 16;
        float p = 0.0f;
        #pragma unroll
        for (int r = 0; r < 16; ++r) {
            p = __fadd_rn(p, S0[base + r]);
            W1[base + r] = p;
        }
        S1[tid] = p;
    }
    __syncthreads();
    // 3c. level2 partials over S1 (43 entries, 3 blocks; last short)
    if (tid < B2) {
        const int base = tid * 16;
        const int hi = (base + 16 < B1) ? base + 16 : B1;
        float p = 0.0f;
        for (int t = base; t < hi; ++t) {
            p = __fadd_rn(p, S1[t]);
            W2[t] = p;
        }
        if (tid == 0) E2[4] = p;             // S2[0]
        if (tid == 1) E2[5] = p;             // S2[1]
    }
    __syncthreads();
    // 3d. base-case exclusive cumsum of S2 -> E2
    if (tid == 0) {
        E2[0] = 0.0f;
        E2[1] = E2[4];
        E2[2] = __fadd_rn(E2[4], E2[5]);
    }
    __syncthreads();
    // 3e. scan1 inclusive (in place over W2): t in [16, 43)
    if (tid >= 16 && tid < B1)
        W2[tid] = __fadd_rn(E2[tid >> 4], W2[tid]);
    __syncthreads();
    // 3f. scan0 inclusive (in place over W1): q in [16, 688)
    if (tid >= 16 && tid < B0)
        W1[tid] = __fadd_rn(W2[(tid >> 4) - 1], W1[tid]);
    __syncthreads();
    // 3g. final combine: i in [16, m)
    for (int i = 16 + tid; i < m; i += NTHREADS)
        cs[i] = __fadd_rn(W1[(i >> 4) - 1], cs[i]);
    __syncthreads();

    // ---- 4. candidate scores + first-max argmax (jnp.argmax semantics) ----
    // score = fl(fl(c*c) * rcp_rn(k))  -- jitted-XLA divide-by-constant form
    const int skip = *skip_p;
    const int ncand = (m + skip - 1) / skip;

    float bs = -1.0f;
    int   bj = 0x7fffffff;
    for (int t = tid; t < ncand; t += NTHREADS) {
        const int j = t * skip;
        const float c = cs[j];
        const float kf = (float)(j + 1);
        const float sc = __fmul_rn(__fmul_rn(c, c), __frcp_rn(kf));
        if (sc > bs) { bs = sc; bj = j; }
    }
    #pragma unroll
    for (int o = 16; o > 0; o >>= 1) {
        float os = __shfl_down_sync(0xffffffffu, bs, o);
        int   oj = __shfl_down_sync(0xffffffffu, bj, o);
        if (os > bs || (os == bs && oj < bj)) { bs = os; bj = oj; }
    }
    if (lane == 0) { reds[wid] = bs; redj[wid] = bj; }
    __syncthreads();
    if (tid < 32) {
        bs = reds[tid]; bj = redj[tid];
        #pragma unroll
        for (int o = 16; o > 0; o >>= 1) {
            float os = __shfl_down_sync(0xffffffffu, bs, o);
            int   oj = __shfl_down_sync(0xffffffffu, bj, o);
            if (os > bs || (os == bs && oj < bj)) { bs = os; bj = oj; }
        }
        if (tid == 0) {
            const int j = bj;
            bc[0] = __fdiv_rn(cs[j], (float)(j + 1));   // v1: true CR division
            bc[1] = SDESC(j);                           // thr
        }
    }
    __syncthreads();

    // ---- 5. output: w_q = (|w| >= thr) ? copysign(v1, w) : 0 ----
    const float v1  = bc[0];
    const float thr = bc[1];
    const float4* wr4  = (const float4*)wr;
    float4*       out4 = (float4*)owr;
    const int m4 = m >> 2;
    for (int i = tid; i < m4; i += NTHREADS) {
        float4 v = wr4[i];
        float4 o;
        o.x = (fabsf(v.x) >= thr) ? copysignf(v1, v.x) : 0.0f;
        o.y = (fabsf(v.y) >= thr) ? copysignf(v1, v.y) : 0.0f;
        o.z = (fabsf(v.z) >= thr) ? copysignf(v1, v.z) : 0.0f;
        o.w = (fabsf(v.w) >= thr) ? copysignf(v1, v.w) : 0.0f;
        out4[i] = o;
    }
    #undef SDESC
}

extern "C" void kernel_launch(void* const* d_in, const int* in_sizes, int n_in,
                              void* d_out, int out_size)
{
    const float* w      = (const float*)d_in[0];
    const int*   skip_p = (const int*)d_in[1];
    float*       out    = (float*)d_out;

    const int m    = M_COLS;
    const int rows = in_sizes[0] / m;

    cudaFuncSetAttribute(lst_ternary_kernel,
                         cudaFuncAttributeMaxDynamicSharedMemorySize,
                         (int)SMEM_BYTES);

    lst_ternary_kernel<<<rows, NTHREADS, SMEM_BYTES>>>(w, skip_p, out, m);
}

// round 16
// speedup vs baseline: 2.3953x; 2.3953x over previous
#include <cuda_runtime.h>
#include <cub/cub.cuh>
#include <math.h>

// Per-row least-squares ternary quantization — BIT-EXACT numerics pinned in R13:
//   exact descending sort of |w| bits; ReduceWindowRewriter(16) recursive cumsum
//   (trailing pad, R9 association); score = fl(fl(c*c)*rcp_rn(k)); v1 = CR divide;
//   first-occurrence argmax; elementwise output.
// R16: revert to CUB sort (R14 base, 835us). RADIX_BITS=5 (7 passes vs 8),
// sorted keys aliased into CUB temp storage (dead after sort), float4 level-0 fold.

#define M_COLS   11008
#define NTHREADS 1024
#define IPT      11
#define NITEMS   (NTHREADS * IPT)   // 11264 >= M_COLS
#define B0       688                // 11008/16
#define B1       43                 // 688/16
#define B2       3

using BlockRadixSortT =
    cub::BlockRadixSort<unsigned int, NTHREADS, IPT, cub::NullType, 5>;

// dynamic smem layout (bytes)
//   [0, 6400)        aux: S0[704] W1[704] S1[48] W2[48] E2[8] reds[32] redj[32] bc[4]
//   [6400, 50432)    cs[M_COLS] floats
//   [50432, ...)     union{ CUB TempStorage ; sd[NITEMS] floats }  (sd written after sort)
static constexpr size_t AX_S0   = 0;
static constexpr size_t AX_W1   = AX_S0 + 704 * 4;
static constexpr size_t AX_S1   = AX_W1 + 704 * 4;
static constexpr size_t AX_W2   = AX_S1 + 48 * 4;
static constexpr size_t AX_E2   = AX_W2 + 48 * 4;
static constexpr size_t AX_REDS = AX_E2 + 8 * 4;
static constexpr size_t AX_REDJ = AX_REDS + 32 * 4;
static constexpr size_t AX_BC   = AX_REDJ + 32 * 4;
static constexpr size_t OFF_CS  = 6400;
static constexpr size_t OFF_SRT = (OFF_CS + M_COLS * 4 + 127) & ~size_t(127);
static constexpr size_t SRT_SZ  =
    sizeof(typename BlockRadixSortT::TempStorage) > (size_t)NITEMS * 4
        ? sizeof(typename BlockRadixSortT::TempStorage) : (size_t)NITEMS * 4;
static constexpr size_t SMEM_BYTES = OFF_SRT + SRT_SZ;

__global__ __launch_bounds__(NTHREADS)
void lst_ternary_kernel(const float* __restrict__ w,
                        const int* __restrict__ skip_p,
                        float* __restrict__ out,
                        int m)
{
    extern __shared__ unsigned char smem[];
    float* S0   = (float*)(smem + AX_S0);
    float* W1   = (float*)(smem + AX_W1);
    float* S1   = (float*)(smem + AX_S1);
    float* W2   = (float*)(smem + AX_W2);
    float* E2   = (float*)(smem + AX_E2);
    float* reds = (float*)(smem + AX_REDS);
    int*   redj = (int*)(smem + AX_REDJ);
    float* bc   = (float*)(smem + AX_BC);
    float* cs   = (float*)(smem + OFF_CS);
    float* sd   = (float*)(smem + OFF_SRT);   // sorted-descending |w|, post-sort alias
    typename BlockRadixSortT::TempStorage* temp =
        (typename BlockRadixSortT::TempStorage*)(smem + OFF_SRT);

    const int tid = threadIdx.x;
    const int row = blockIdx.x;
    const float* wr  = w   + (long long)row * m;
    float*       owr = out + (long long)row * m;

    // ---- 1. load keys = bits of |w| (monotone for nonneg); pads = 0 ----
    unsigned int keys[IPT];
    #pragma unroll
    for (int i = 0; i < IPT; ++i) {
        const int idx = i * NTHREADS + tid;
        keys[i] = (idx < m) ? (__float_as_uint(wr[idx]) & 0x7fffffffu) : 0u;
    }

    // ---- 2. exact radix sort, descending, 5-bit digits (7 passes) ----
    BlockRadixSortT(*temp).SortDescending(keys, 0, 31);
    __syncthreads();                         // temp dead; safe to overwrite with sd
    // blocked output: thread t holds descending ranks [t*IPT, (t+1)*IPT)
    #pragma unroll
    for (int i = 0; i < IPT; ++i)
        sd[tid * IPT + i] = __uint_as_float(keys[i]);
    __syncthreads();
    // sd[i] = i-th largest; pads (=0) land at ranks >= m.

    // ---- 3. ReduceWindowRewriter(16), recursive, trailing pad (R9 assoc) ----
    // 3a. level0 per-16 fold-left, vectorized (identical add order)
    if (tid < B0) {
        const float4* p4 = (const float4*)(sd + tid * 16);
        float4 q0 = p4[0], q1 = p4[1], q2 = p4[2], q3 = p4[3];
        float c[16];
        float p = 0.0f;
        p = __fadd_rn(p, q0.x); c[0]  = p;
        p = __fadd_rn(p, q0.y); c[1]  = p;
        p = __fadd_rn(p, q0.z); c[2]  = p;
        p = __fadd_rn(p, q0.w); c[3]  = p;
        p = __fadd_rn(p, q1.x); c[4]  = p;
        p = __fadd_rn(p, q1.y); c[5]  = p;
        p = __fadd_rn(p, q1.z); c[6]  = p;
        p = __fadd_rn(p, q1.w); c[7]  = p;
        p = __fadd_rn(p, q2.x); c[8]  = p;
        p = __fadd_rn(p, q2.y); c[9]  = p;
        p = __fadd_rn(p, q2.z); c[10] = p;
        p = __fadd_rn(p, q2.w); c[11] = p;
        p = __fadd_rn(p, q3.x); c[12] = p;
        p = __fadd_rn(p, q3.y); c[13] = p;
        p = __fadd_rn(p, q3.z); c[14] = p;
        p = __fadd_rn(p, q3.w); c[15] = p;
        float4* cs4 = (float4*)(cs + tid * 16);
        cs4[0] = make_float4(c[0],  c[1],  c[2],  c[3]);
        cs4[1] = make_float4(c[4],  c[5],  c[6],  c[7]);
        cs4[2] = make_float4(c[8],  c[9],  c[10], c[11]);
        cs4[3] = make_float4(c[12], c[13], c[14], c[15]);
        S0[tid] = p;
    }
    __syncthreads();
    // 3b. level1 partials over S0 (688 = 43*16 exact)
    if (tid < B1) {
        const int base = tid * 16;
        float p = 0.0f;
        #pragma unroll
        for (int r = 0; r < 16; ++r) {
            p = __fadd_rn(p, S0[base + r]);
            W1[base + r] = p;
        }
        S1[tid] = p;
    }
    __syncthreads();
    // 3c. level2 partials over S1 (43 entries, 3 blocks; last short)
    if (tid < B2) {
        const int base = tid * 16;
        const int hi = (base + 16 < B1) ? base + 16 : B1;
        float p = 0.0f;
        for (int t = base; t < hi; ++t) {
            p = __fadd_rn(p, S1[t]);
            W2[t] = p;
        }
        if (tid == 0) E2[4] = p;             // S2[0]
        if (tid == 1) E2[5] = p;             // S2[1]
    }
    __syncthreads();
    // 3d. base-case exclusive cumsum of S2 -> E2
    if (tid == 0) {
        E2[0] = 0.0f;
        E2[1] = E2[4];
        E2[2] = __fadd_rn(E2[4], E2[5]);
    }
    __syncthreads();
    // 3e. scan1 inclusive (in place over W2): t in [16, 43)
    if (tid >= 16 && tid < B1)
        W2[tid] = __fadd_rn(E2[tid >> 4], W2[tid]);
    __syncthreads();
    // 3f. scan0 inclusive (in place over W1): q in [16, 688)
    if (tid >= 16 && tid < B0)
        W1[tid] = __fadd_rn(W2[(tid >> 4) - 1], W1[tid]);
    __syncthreads();
    // 3g. final combine: i in [16, m)
    for (int i = 16 + tid; i < m; i += NTHREADS)
        cs[i] = __fadd_rn(W1[(i >> 4) - 1], cs[i]);
    __syncthreads();

    // ---- 4. candidate scores + first-max argmax (jnp.argmax semantics) ----
    // score = fl(fl(c*c) * rcp_rn(k))  -- jitted-XLA divide-by-constant form
    const int skip = *skip_p;
    const int ncand = (m + skip - 1) / skip;

    float bs = -1.0f;
    int   bj = 0x7fffffff;
    for (int t = tid; t < ncand; t += NTHREADS) {
        const int j = t * skip;
        const float c = cs[j];
        const float kf = (float)(j + 1);
        const float sc = __fmul_rn(__fmul_rn(c, c), __frcp_rn(kf));
        if (sc > bs) { bs = sc; bj = j; }
    }
    #pragma unroll
    for (int o = 16; o > 0; o >>= 1) {
        float os = __shfl_down_sync(0xffffffffu, bs, o);
        int   oj = __shfl_down_sync(0xffffffffu, bj, o);
        if (os > bs || (os == bs && oj < bj)) { bs = os; bj = oj; }
    }
    if ((tid & 31) == 0) { reds[tid >> 5] = bs; redj[tid >> 5] = bj; }
    __syncthreads();
    if (tid < 32) {
        bs = reds[tid]; bj = redj[tid];
        #pragma unroll
        for (int o = 16; o > 0; o >>= 1) {
            float os = __shfl_down_sync(0xffffffffu, bs, o);
            int   oj = __shfl_down_sync(0xffffffffu, bj, o);
            if (os > bs || (os == bs && oj < bj)) { bs = os; bj = oj; }
        }
        if (tid == 0) {
            const int j = bj;
            bc[0] = __fdiv_rn(cs[j], (float)(j + 1));   // v1: true CR division
            bc[1] = sd[j];                              // thr
        }
    }
    __syncthreads();

    // ---- 5. output: w_q = (|w| >= thr) ? copysign(v1, w) : 0 ----
    const float v1  = bc[0];
    const float thr = bc[1];
    const float4* wr4  = (const float4*)wr;
    float4*       out4 = (float4*)owr;
    const int m4 = m >> 2;
    for (int i = tid; i < m4; i += NTHREADS) {
        float4 v = wr4[i];
        float4 o;
        o.x = (fabsf(v.x) >= thr) ? copysignf(v1, v.x) : 0.0f;
        o.y = (fabsf(v.y) >= thr) ? copysignf(v1, v.y) : 0.0f;
        o.z = (fabsf(v.z) >= thr) ? copysignf(v1, v.z) : 0.0f;
        o.w = (fabsf(v.w) >= thr) ? copysignf(v1, v.w) : 0.0f;
        out4[i] = o;
    }
}

extern "C" void kernel_launch(void* const* d_in, const int* in_sizes, int n_in,
                              void* d_out, int out_size)
{
    const float* w      = (const float*)d_in[0];
    const int*   skip_p = (const int*)d_in[1];
    float*       out    = (float*)d_out;

    const int m    = M_COLS;
    const int rows = in_sizes[0] / m;

    cudaFuncSetAttribute(lst_ternary_kernel,
                         cudaFuncAttributeMaxDynamicSharedMemorySize,
                         (int)SMEM_BYTES);

    lst_ternary_kernel<<<rows, NTHREADS, SMEM_BYTES>>>(w, skip_p, out, m);
}

// round 17
// speedup vs baseline: 2.5178x; 1.0511x over previous
#include <cuda_runtime.h>
#include <cub/cub.cuh>
#include <math.h>

// Per-row least-squares ternary quantization — BIT-EXACT numerics pinned in R13:
//   exact descending sort of |w| bits; ReduceWindowRewriter(16) recursive cumsum
//   (trailing pad, R9 association); score = fl(fl(c*c)*rcp_rn(k)); v1 = CR divide;
//   first-occurrence argmax; elementwise output.
// R17: key-range compression. key' = key - kmin (order-preserving, exact);
// all key' fit in E = 32-clz(kmax-kmin) bits (E <= 30 for this data), so CUB
// sorts bits [0,E) only: 6 ranking passes instead of 7. Per-block E from an
// exact u32 min/max reduction. sd reconstructed as key' + kmin (same bits).

#define M_COLS   11008
#define NTHREADS 1024
#define IPT      11
#define NITEMS   (NTHREADS * IPT)   // 11264 >= M_COLS
#define B0       688                // 11008/16
#define B1       43                 // 688/16
#define B2       3

using BlockRadixSortT =
    cub::BlockRadixSort<unsigned int, NTHREADS, IPT, cub::NullType, 5>;

// dynamic smem layout (bytes)
static constexpr size_t AX_S0   = 0;
static constexpr size_t AX_W1   = AX_S0 + 704 * 4;
static constexpr size_t AX_S1   = AX_W1 + 704 * 4;
static constexpr size_t AX_W2   = AX_S1 + 48 * 4;
static constexpr size_t AX_E2   = AX_W2 + 48 * 4;
static constexpr size_t AX_REDS = AX_E2 + 8 * 4;    // pre-sort: u32 warp mins
static constexpr size_t AX_REDJ = AX_REDS + 32 * 4; // pre-sort: u32 warp maxs
static constexpr size_t AX_BC   = AX_REDJ + 32 * 4; // [0]=v1/[1]=thr ; pre-sort [2]=kmin,[3]=E
static constexpr size_t OFF_CS  = 6400;
static constexpr size_t OFF_SRT = (OFF_CS + M_COLS * 4 + 127) & ~size_t(127);
static constexpr size_t SRT_SZ  =
    sizeof(typename BlockRadixSortT::TempStorage) > (size_t)NITEMS * 4
        ? sizeof(typename BlockRadixSortT::TempStorage) : (size_t)NITEMS * 4;
static constexpr size_t SMEM_BYTES = OFF_SRT + SRT_SZ;

__global__ __launch_bounds__(NTHREADS)
void lst_ternary_kernel(const float* __restrict__ w,
                        const int* __restrict__ skip_p,
                        float* __restrict__ out,
                        int m)
{
    extern __shared__ unsigned char smem[];
    float* S0   = (float*)(smem + AX_S0);
    float* W1   = (float*)(smem + AX_W1);
    float* S1   = (float*)(smem + AX_S1);
    float* W2   = (float*)(smem + AX_W2);
    float* E2   = (float*)(smem + AX_E2);
    float* reds = (float*)(smem + AX_REDS);
    int*   redj = (int*)(smem + AX_REDJ);
    float* bc   = (float*)(smem + AX_BC);
    unsigned int* umin = (unsigned int*)(smem + AX_REDS);
    unsigned int* umax = (unsigned int*)(smem + AX_REDJ);
    unsigned int* ubc  = (unsigned int*)(smem + AX_BC);
    float* cs   = (float*)(smem + OFF_CS);
    float* sd   = (float*)(smem + OFF_SRT);   // sorted-descending |w|, post-sort alias
    typename BlockRadixSortT::TempStorage* temp =
        (typename BlockRadixSortT::TempStorage*)(smem + OFF_SRT);

    const int tid = threadIdx.x;
    const int row = blockIdx.x;
    const float* wr  = w   + (long long)row * m;
    float*       owr = out + (long long)row * m;

    // ---- 1. load keys = bits of |w| (monotone for nonneg); pads = 0 ----
    unsigned int keys[IPT];
    #pragma unroll
    for (int i = 0; i < IPT; ++i) {
        const int idx = i * NTHREADS + tid;
        keys[i] = (idx < m) ? (__float_as_uint(wr[idx]) & 0x7fffffffu) : 0u;
    }

    // ---- 1b. exact block min/max over REAL keys -> kmin, E ----
    {
        unsigned kmn = 0xffffffffu, kmx = 0u;
        #pragma unroll
        for (int i = 0; i < IPT; ++i) {
            const int idx = i * NTHREADS + tid;
            if (idx < m) {
                kmn = min(kmn, keys[i]);
                kmx = max(kmx, keys[i]);
            }
        }
        #pragma unroll
        for (int o = 16; o > 0; o >>= 1) {
            kmn = min(kmn, __shfl_xor_sync(0xffffffffu, kmn, o));
            kmx = max(kmx, __shfl_xor_sync(0xffffffffu, kmx, o));
        }
        if ((tid & 31) == 0) { umin[tid >> 5] = kmn; umax[tid >> 5] = kmx; }
        __syncthreads();
        if (tid < 32) {
            kmn = umin[tid]; kmx = umax[tid];
            #pragma unroll
            for (int o = 16; o > 0; o >>= 1) {
                kmn = min(kmn, __shfl_xor_sync(0xffffffffu, kmn, o));
                kmx = max(kmx, __shfl_xor_sync(0xffffffffu, kmx, o));
            }
            if (tid == 0) {
                const unsigned diff = kmx - kmn;
                int E = 32 - __clz(diff | 1u);   // >= 1
                ubc[2] = kmn;
                ubc[3] = (unsigned)E;
            }
        }
        __syncthreads();
    }
    const unsigned kmin = ubc[2];
    const int      ebit = (int)ubc[3];
    __syncthreads();   // all reads of ubc done before CUB/aux reuse

    // transform: order-preserving, all bits above ebit become 0
    #pragma unroll
    for (int i = 0; i < IPT; ++i) {
        const int idx = i * NTHREADS + tid;
        keys[i] = (idx < m) ? (keys[i] - kmin) : 0u;
    }

    // ---- 2. exact radix sort, descending, bits [0, ebit) only ----
    BlockRadixSortT(*temp).SortDescending(keys, 0, ebit);
    __syncthreads();                         // temp dead; safe to overwrite with sd
    #pragma unroll
    for (int i = 0; i < IPT; ++i)
        sd[tid * IPT + i] = __uint_as_float(keys[i] + kmin);
    __syncthreads();
    // sd[i] = i-th largest |w| bits (exact); ranks >= m never read.

    // ---- 3. ReduceWindowRewriter(16), recursive, trailing pad (R9 assoc) ----
    // 3a. level0 per-16 fold-left, vectorized (identical add order)
    if (tid < B0) {
        const float4* p4 = (const float4*)(sd + tid * 16);
        float4 q0 = p4[0], q1 = p4[1], q2 = p4[2], q3 = p4[3];
        float c[16];
        float p = 0.0f;
        p = __fadd_rn(p, q0.x); c[0]  = p;
        p = __fadd_rn(p, q0.y); c[1]  = p;
        p = __fadd_rn(p, q0.z); c[2]  = p;
        p = __fadd_rn(p, q0.w); c[3]  = p;
        p = __fadd_rn(p, q1.x); c[4]  = p;
        p = __fadd_rn(p, q1.y); c[5]  = p;
        p = __fadd_rn(p, q1.z); c[6]  = p;
        p = __fadd_rn(p, q1.w); c[7]  = p;
        p = __fadd_rn(p, q2.x); c[8]  = p;
        p = __fadd_rn(p, q2.y); c[9]  = p;
        p = __fadd_rn(p, q2.z); c[10] = p;
        p = __fadd_rn(p, q2.w); c[11] = p;
        p = __fadd_rn(p, q3.x); c[12] = p;
        p = __fadd_rn(p, q3.y); c[13] = p;
        p = __fadd_rn(p, q3.z); c[14] = p;
        p = __fadd_rn(p, q3.w); c[15] = p;
        float4* cs4 = (float4*)(cs + tid * 16);
        cs4[0] = make_float4(c[0],  c[1],  c[2],  c[3]);
        cs4[1] = make_float4(c[4],  c[5],  c[6],  c[7]);
        cs4[2] = make_float4(c[8],  c[9],  c[10], c[11]);
        cs4[3] = make_float4(c[12], c[13], c[14], c[15]);
        S0[tid] = p;
    }
    __syncthreads();
    // 3b. level1 partials over S0 (688 = 43*16 exact)
    if (tid < B1) {
        const int base = tid * 16;
        float p = 0.0f;
        #pragma unroll
        for (int r = 0; r < 16; ++r) {
            p = __fadd_rn(p, S0[base + r]);
            W1[base + r] = p;
        }
        S1[tid] = p;
    }
    __syncthreads();
    // 3c. level2 partials over S1 (43 entries, 3 blocks; last short)
    if (tid < B2) {
        const int base = tid * 16;
        const int hi = (base + 16 < B1) ? base + 16 : B1;
        float p = 0.0f;
        for (int t = base; t < hi; ++t) {
            p = __fadd_rn(p, S1[t]);
            W2[t] = p;
        }
        if (tid == 0) E2[4] = p;             // S2[0]
        if (tid == 1) E2[5] = p;             // S2[1]
    }
    __syncthreads();
    // 3d. base-case exclusive cumsum of S2 -> E2
    if (tid == 0) {
        E2[0] = 0.0f;
        E2[1] = E2[4];
        E2[2] = __fadd_rn(E2[4], E2[5]);
    }
    __syncthreads();
    // 3e. scan1 inclusive (in place over W2): t in [16, 43)
    if (tid >= 16 && tid < B1)
        W2[tid] = __fadd_rn(E2[tid >> 4], W2[tid]);
    __syncthreads();
    // 3f. scan0 inclusive (in place over W1): q in [16, 688)
    if (tid >= 16 && tid < B0)
        W1[tid] = __fadd_rn(W2[(tid >> 4) - 1], W1[tid]);
    __syncthreads();
    // 3g. final combine: i in [16, m)
    for (int i = 16 + tid; i < m; i += NTHREADS)
        cs[i] = __fadd_rn(W1[(i >> 4) - 1], cs[i]);
    __syncthreads();

    // ---- 4. candidate scores + first-max argmax (jnp.argmax semantics) ----
    // score = fl(fl(c*c) * rcp_rn(k))  -- jitted-XLA divide-by-constant form
    const int skip = *skip_p;
    const int ncand = (m + skip - 1) / skip;

    float bs = -1.0f;
    int   bj = 0x7fffffff;
    for (int t = tid; t < ncand; t += NTHREADS) {
        const int j = t * skip;
        const float c = cs[j];
        const float kf = (float)(j + 1);
        const float sc = __fmul_rn(__fmul_rn(c, c), __frcp_rn(kf));
        if (sc > bs) { bs = sc; bj = j; }
    }
    #pragma unroll
    for (int o = 16; o > 0; o >>= 1) {
        float os = __shfl_down_sync(0xffffffffu, bs, o);
        int   oj = __shfl_down_sync(0xffffffffu, bj, o);
        if (os > bs || (os == bs && oj < bj)) { bs = os; bj = oj; }
    }
    if ((tid & 31) == 0) { reds[tid >> 5] = bs; redj[tid >> 5] = bj; }
    __syncthreads();
    if (tid < 32) {
        bs = reds[tid]; bj = redj[tid];
        #pragma unroll
        for (int o = 16; o > 0; o >>= 1) {
            float os = __shfl_down_sync(0xffffffffu, bs, o);
            int   oj = __shfl_down_sync(0xffffffffu, bj, o);
            if (os > bs || (os == bs && oj < bj)) { bs = os; bj = oj; }
        }
        if (tid == 0) {
            const int j = bj;
            bc[0] = __fdiv_rn(cs[j], (float)(j + 1));   // v1: true CR division
            bc[1] = sd[j];                              // thr
        }
    }
    __syncthreads();

    // ---- 5. output: w_q = (|w| >= thr) ? copysign(v1, w) : 0 ----
    const float v1  = bc[0];
    const float thr = bc[1];
    const float4* wr4  = (const float4*)wr;
    float4*       out4 = (float4*)owr;
    const int m4 = m >> 2;
    for (int i = tid; i < m4; i += NTHREADS) {
        float4 v = wr4[i];
        float4 o;
        o.x = (fabsf(v.x) >= thr) ? copysignf(v1, v.x) : 0.0f;
        o.y = (fabsf(v.y) >= thr) ? copysignf(v1, v.y) : 0.0f;
        o.z = (fabsf(v.z) >= thr) ? copysignf(v1, v.z) : 0.0f;
        o.w = (fabsf(v.w) >= thr) ? copysignf(v1, v.w) : 0.0f;
        out4[i] = o;
    }
}

extern "C" void kernel_launch(void* const* d_in, const int* in_sizes, int n_in,
                              void* d_out, int out_size)
{
    const float* w      = (const float*)d_in[0];
    const int*   skip_p = (const int*)d_in[1];
    float*       out    = (float*)d_out;

    const int m    = M_COLS;
    const int rows = in_sizes[0] / m;

    cudaFuncSetAttribute(lst_ternary_kernel,
                         cudaFuncAttributeMaxDynamicSharedMemorySize,
                         (int)SMEM_BYTES);

    lst_ternary_kernel<<<rows, NTHREADS, SMEM_BYTES>>>(w, skip_p, out, m);
}